// round 12
// baseline (speedup 1.0000x reference)
#include <cuda_runtime.h>
#include <cuda_fp16.h>
#include <cstdint>

// ---------------------------------------------------------------------------
// GNN: L x { agg = scatter_add(h[src]*ew, dst); h = PReLU(LN(agg@Wrel + h@Wroot + b)) }
// then logits = LN(relu(h@W1+b1)) @ W2 + b2
// R12: edge-balanced gather (warp per 256-edge slice of the dst-sorted edge
//      list, one red.global.add.v4 per dst-run) + uint4 edge records.
//      Layer/classifier kernels identical to R10/R11 (proven).
// ---------------------------------------------------------------------------

#define MAXN 100000
#define MAXE 1600000
#define DD   128
#define KE   256      // edges per gather warp

__device__ float  g_buf0[MAXN * DD];
__device__ float  g_buf1[MAXN * DD];
__device__ float  g_agg [MAXN * DD];
__device__ __half g_h16 [MAXN * DD];
__device__ int    g_cnt [MAXN];       // zero at entry of every call (see place)
__device__ int    g_off [MAXN + 1];
__device__ int    g_bsum[128];
__device__ uint4  g_epack[MAXE];      // {src, weight-bits, dst, pad}

__device__ __forceinline__ uint32_t tf32c(float f) {
    uint32_t r; asm("cvt.rna.tf32.f32 %0, %1;" : "=r"(r) : "f"(f)); return r;
}
__device__ __forceinline__ void mma8(float c[4], uint32_t a0, uint32_t a1,
                                     uint32_t a2, uint32_t a3,
                                     uint32_t b0, uint32_t b1) {
    asm volatile(
        "mma.sync.aligned.m16n8k8.row.col.f32.tf32.tf32.f32 "
        "{%0,%1,%2,%3},{%4,%5,%6,%7},{%8,%9},{%0,%1,%2,%3};"
        : "+f"(c[0]), "+f"(c[1]), "+f"(c[2]), "+f"(c[3])
        : "r"(a0), "r"(a1), "r"(a2), "r"(a3), "r"(b0), "r"(b1));
}

// ======================= CSR build (no memsets) ============================
__global__ void hist_kernel(const int* __restrict__ ei, int* __restrict__ cnt, int E) {
    int e = blockIdx.x * blockDim.x + threadIdx.x;
    if (e < E) atomicAdd(cnt + __ldg(ei + E + e), 1);
}
__global__ void scan1_kernel(const int* __restrict__ cnt, int* __restrict__ off,
                             int* __restrict__ bsum, int N) {
    __shared__ int s[1024];
    int tid = threadIdx.x;
    int i = blockIdx.x * 1024 + tid;
    int v = (i < N) ? cnt[i] : 0;
    s[tid] = v; __syncthreads();
    #pragma unroll
    for (int d = 1; d < 1024; d <<= 1) {
        int t = (tid >= d) ? s[tid - d] : 0;
        __syncthreads();
        s[tid] += t;
        __syncthreads();
    }
    if (i < N) off[i] = s[tid] - v;
    if (tid == 1023) bsum[blockIdx.x] = s[1023];
}
__global__ void scan2_kernel(int* __restrict__ bsum, int* __restrict__ off,
                             int NB, int N) {
    __shared__ int s[128];
    int tid = threadIdx.x;
    int v = (tid < NB) ? bsum[tid] : 0;
    s[tid] = v; __syncthreads();
    #pragma unroll
    for (int d = 1; d < 128; d <<= 1) {
        int t = (tid >= d) ? s[tid - d] : 0;
        __syncthreads();
        s[tid] += t;
        __syncthreads();
    }
    if (tid < NB) bsum[tid] = s[tid] - v;
    if (tid == 127) off[N] = s[127];
}
__global__ void place_kernel(const int* __restrict__ ei, const float* __restrict__ ew,
                             const int* __restrict__ off, const int* __restrict__ bsum,
                             int* __restrict__ cursor, uint4* __restrict__ epack, int E) {
    int e = blockIdx.x * blockDim.x + threadIdx.x;
    if (e >= E) return;
    int src = __ldg(ei + e);
    int dst = __ldg(ei + E + e);
    int pos = off[dst] + bsum[dst >> 10] + (atomicSub(cursor + dst, 1) - 1);
    epack[pos] = make_uint4((uint32_t)src, __float_as_uint(__ldg(ew + e)),
                            (uint32_t)dst, 0u);
}

// ======================= fp32 -> fp16 convert ==============================
__global__ void to_half_kernel(const float4* __restrict__ x,
                               uint2* __restrict__ y, int n4) {
    int i = blockIdx.x * blockDim.x + threadIdx.x;
    if (i >= n4) return;
    float4 v = x[i];
    __half2 a = __floats2half2_rn(v.x, v.y);
    __half2 b = __floats2half2_rn(v.z, v.w);
    y[i] = make_uint2(*(uint32_t*)&a, *(uint32_t*)&b);
}

// ===== Aggregation: edge-balanced, warp per KE-edge slice, red per run =====
// agg must be zeroed before this kernel (cudaMemsetAsync). Edges are sorted
// by dst (CSR), so each warp's slice is a sequence of dst-runs; one vector
// reduction per run (plus one per cut run at each slice boundary).
__global__ __launch_bounds__(256)
void gather_kernel(const __half* __restrict__ h16,
                   const uint4*  __restrict__ ep,
                   float*        __restrict__ agg, int E) {
    int gw   = (blockIdx.x * blockDim.x + threadIdx.x) >> 5;
    int lane = threadIdx.x & 31;
    int wBeg = gw * KE;
    if (wBeg >= E) return;
    int wEnd = min(wBeg + KE, E);

    uint4 rec = __ldg(ep + wBeg);
    uint32_t d = rec.z;
    float4 acc = {0.f, 0.f, 0.f, 0.f};

    for (int e = wBeg; e < wEnd; e++) {
        uint4 nrec;
        bool hasNext = (e + 1 < wEnd);
        if (hasNext) nrec = __ldg(ep + e + 1);

        float w0 = __uint_as_float(rec.y);
        uint2 r = *reinterpret_cast<const uint2*>(h16 + (size_t)rec.x * DD + lane * 4);
        float2 a0 = __half22float2(*(__half2*)&r.x);
        float2 b0 = __half22float2(*(__half2*)&r.y);
        acc.x = fmaf(w0, a0.x, acc.x);
        acc.y = fmaf(w0, a0.y, acc.y);
        acc.z = fmaf(w0, b0.x, acc.z);
        acc.w = fmaf(w0, b0.y, acc.w);

        if (hasNext) {
            if (nrec.z != d) {
                float* ap = agg + (size_t)d * DD + lane * 4;
                asm volatile("red.global.add.v4.f32 [%0], {%1,%2,%3,%4};"
                             :: "l"(ap), "f"(acc.x), "f"(acc.y), "f"(acc.z), "f"(acc.w)
                             : "memory");
                acc = make_float4(0.f, 0.f, 0.f, 0.f);
                d = nrec.z;
            }
            rec = nrec;
        }
    }
    float* ap = agg + (size_t)d * DD + lane * 4;
    asm volatile("red.global.add.v4.f32 [%0], {%1,%2,%3,%4};"
                 :: "l"(ap), "f"(acc.x), "f"(acc.y), "f"(acc.z), "f"(acc.w)
                 : "memory");
}

// ============== Layer GEMM via warp-level mma.sync tf32 (R7/R8 core) =======
__global__ __launch_bounds__(256, 1)
void layer_mma_kernel(const float* __restrict__ hin,
                      const float* __restrict__ agg,
                      const float* __restrict__ Wrel,
                      const float* __restrict__ Wroot,
                      const float* __restrict__ bias,
                      const float* __restrict__ lng,
                      const float* __restrict__ lnb,
                      const float* __restrict__ alpha,
                      float*       __restrict__ hout,
                      __half*      __restrict__ hout16,
                      int N) {
    extern __shared__ uint32_t smemu[];
    uint32_t* sBr = smemu;            // 64 KB Wrel fragments
    uint32_t* sBo = smemu + 16384;    // 64 KB Wroot fragments
    __shared__ float sBias[128], sG[128], sB2[128];

    int tid = threadIdx.x, wid = tid >> 5, lane = tid & 31;
    int g = lane >> 2, t = lane & 3;

    for (int idx = tid; idx < 4096; idx += 256) {
        int k = idx >> 5, n4 = (idx & 31) * 4;
        float4 vr = *reinterpret_cast<const float4*>(Wrel  + (size_t)k * 128 + n4);
        float4 vo = *reinterpret_cast<const float4*>(Wroot + (size_t)k * 128 + n4);
        int kk = k >> 3, t8 = k & 7, breg = t8 >> 2, tt = t8 & 3;
        int j = ((kk & 1) << 1) + breg, kkp = kk >> 1;
        float vrA[4] = {vr.x, vr.y, vr.z, vr.w};
        float voA[4] = {vo.x, vo.y, vo.z, vo.w};
        #pragma unroll
        for (int m = 0; m < 4; m++) {
            int n = n4 + m, nt = n >> 3, gg = n & 7;
            int base = ((nt * 8 + kkp) * 32 + gg * 4 + tt) * 4 + j;
            sBr[base] = tf32c(vrA[m]);
            sBo[base] = tf32c(voA[m]);
        }
    }
    if (tid < 128) {
        sBias[tid] = __ldg(bias + tid);
        sG[tid]    = __ldg(lng + tid);
        sB2[tid]   = __ldg(lnb + tid);
    }
    __syncthreads();

    float al = __ldg(alpha);
    int numUnits = (N + 31) >> 5;
    int ustride  = gridDim.x * 8;

    for (int unit = blockIdx.x * 8 + wid; unit < numUnits; unit += ustride) {
        int R0 = unit * 32;
        float c[2][16][4];
        #pragma unroll
        for (int mt = 0; mt < 2; mt++)
            #pragma unroll
            for (int nt = 0; nt < 16; nt++)
                #pragma unroll
                for (int j = 0; j < 4; j++) c[mt][nt][j] = 0.f;

        #pragma unroll
        for (int half = 0; half < 2; half++) {
            const float*    src = half ? hin : agg;
            const uint32_t* sBf = half ? sBo : sBr;

            const float* rp[2][2];
            bool rv[2][2];
            #pragma unroll
            for (int mt = 0; mt < 2; mt++)
                #pragma unroll
                for (int rh = 0; rh < 2; rh++) {
                    int r = R0 + mt * 16 + g + 8 * rh;
                    rv[mt][rh] = r < N;
                    rp[mt][rh] = src + (size_t)r * 128 + t;
                }

            uint32_t a[2][2][8];
            #pragma unroll
            for (int mt = 0; mt < 2; mt++) {
                #pragma unroll
                for (int q = 0; q < 2; q++) {
                    int o = q * 8;
                    a[0][mt][q*4+0] = tf32c(rv[mt][0] ? rp[mt][0][o]     : 0.f);
                    a[0][mt][q*4+1] = tf32c(rv[mt][1] ? rp[mt][1][o]     : 0.f);
                    a[0][mt][q*4+2] = tf32c(rv[mt][0] ? rp[mt][0][o + 4] : 0.f);
                    a[0][mt][q*4+3] = tf32c(rv[mt][1] ? rp[mt][1][o + 4] : 0.f);
                }
            }

            #pragma unroll
            for (int kkp = 0; kkp < 8; kkp++) {
                int cur = kkp & 1;
                if (kkp < 7) {
                    int kb = (kkp + 1) * 16;
                    #pragma unroll
                    for (int mt = 0; mt < 2; mt++) {
                        #pragma unroll
                        for (int q = 0; q < 2; q++) {
                            int o = kb + q * 8;
                            a[cur^1][mt][q*4+0] = tf32c(rv[mt][0] ? rp[mt][0][o]     : 0.f);
                            a[cur^1][mt][q*4+1] = tf32c(rv[mt][1] ? rp[mt][1][o]     : 0.f);
                            a[cur^1][mt][q*4+2] = tf32c(rv[mt][0] ? rp[mt][0][o + 4] : 0.f);
                            a[cur^1][mt][q*4+3] = tf32c(rv[mt][1] ? rp[mt][1][o + 4] : 0.f);
                        }
                    }
                }
                #pragma unroll
                for (int nt = 0; nt < 16; nt++) {
                    uint4 bv = *reinterpret_cast<const uint4*>(
                        sBf + ((nt * 8 + kkp) * 32 + lane) * 4);
                    mma8(c[0][nt], a[cur][0][0], a[cur][0][1], a[cur][0][2], a[cur][0][3], bv.x, bv.y);
                    mma8(c[0][nt], a[cur][0][4], a[cur][0][5], a[cur][0][6], a[cur][0][7], bv.z, bv.w);
                    mma8(c[1][nt], a[cur][1][0], a[cur][1][1], a[cur][1][2], a[cur][1][3], bv.x, bv.y);
                    mma8(c[1][nt], a[cur][1][4], a[cur][1][5], a[cur][1][6], a[cur][1][7], bv.z, bv.w);
                }
            }
        }

        // ---- epilogue: bias + LN + PReLU + fp32/fp16 store ----
        #pragma unroll
        for (int mt = 0; mt < 2; mt++) {
            #pragma unroll
            for (int rh = 0; rh < 2; rh++) {
                int r = R0 + mt * 16 + g + 8 * rh;
                float s = 0.f;
                #pragma unroll
                for (int nt = 0; nt < 16; nt++) {
                    int col = nt * 8 + 2 * t;
                    c[mt][nt][2*rh]   += sBias[col];
                    c[mt][nt][2*rh+1] += sBias[col + 1];
                    s += c[mt][nt][2*rh] + c[mt][nt][2*rh+1];
                }
                s += __shfl_xor_sync(0xffffffffu, s, 1);
                s += __shfl_xor_sync(0xffffffffu, s, 2);
                float mu = s * 0.0078125f;
                float q = 0.f;
                #pragma unroll
                for (int nt = 0; nt < 16; nt++) {
                    c[mt][nt][2*rh]   -= mu;
                    c[mt][nt][2*rh+1] -= mu;
                    q = fmaf(c[mt][nt][2*rh],   c[mt][nt][2*rh],
                        fmaf(c[mt][nt][2*rh+1], c[mt][nt][2*rh+1], q));
                }
                q += __shfl_xor_sync(0xffffffffu, q, 1);
                q += __shfl_xor_sync(0xffffffffu, q, 2);
                float rstd = rsqrtf(q * 0.0078125f + 1e-5f);
                if (r < N) {
                    #pragma unroll
                    for (int nt = 0; nt < 16; nt++) {
                        int col = nt * 8 + 2 * t;
                        float y0 = c[mt][nt][2*rh]   * rstd * sG[col]     + sB2[col];
                        float y1 = c[mt][nt][2*rh+1] * rstd * sG[col + 1] + sB2[col + 1];
                        y0 = y0 >= 0.f ? y0 : al * y0;
                        y1 = y1 >= 0.f ? y1 : al * y1;
                        *reinterpret_cast<float2*>(hout + (size_t)r * 128 + col) =
                            make_float2(y0, y1);
                        *reinterpret_cast<__half2*>(hout16 + (size_t)r * 128 + col) =
                            __floats2half2_rn(y0, y1);
                    }
                }
            }
        }
    }
}

// ============== Classifier via warp-level mma.sync tf32 ====================
__global__ __launch_bounds__(256, 1)
void cls_mma_kernel(const float* __restrict__ hin,
                    const float* __restrict__ W1,
                    const float* __restrict__ b1,
                    const float* __restrict__ lng,
                    const float* __restrict__ lnb,
                    const float* __restrict__ W2,
                    const float* __restrict__ b2,
                    float*       __restrict__ out,
                    int N) {
    extern __shared__ uint32_t smemu[];
    uint32_t* sBf = smemu;            // 64 KB W1 fragments
    __shared__ float sBias[128], sG[128], sB2[128], sW2[256];

    int tid = threadIdx.x, wid = tid >> 5, lane = tid & 31;
    int g = lane >> 2, t = lane & 3;

    for (int idx = tid; idx < 4096; idx += 256) {
        int k = idx >> 5, n4 = (idx & 31) * 4;
        float4 vw = *reinterpret_cast<const float4*>(W1 + (size_t)k * 128 + n4);
        int kk = k >> 3, t8 = k & 7, breg = t8 >> 2, tt = t8 & 3;
        int j = ((kk & 1) << 1) + breg, kkp = kk >> 1;
        float vA[4] = {vw.x, vw.y, vw.z, vw.w};
        #pragma unroll
        for (int m = 0; m < 4; m++) {
            int n = n4 + m, nt = n >> 3, gg = n & 7;
            sBf[((nt * 8 + kkp) * 32 + gg * 4 + tt) * 4 + j] = tf32c(vA[m]);
        }
    }
    if (tid < 128) {
        sBias[tid] = __ldg(b1 + tid);
        sG[tid]    = __ldg(lng + tid);
        sB2[tid]   = __ldg(lnb + tid);
        sW2[tid * 2]     = __ldg(W2 + tid * 2);
        sW2[tid * 2 + 1] = __ldg(W2 + tid * 2 + 1);
    }
    __syncthreads();

    float b20 = __ldg(b2 + 0), b21 = __ldg(b2 + 1);
    int numUnits = (N + 31) >> 5;
    int ustride  = gridDim.x * 8;

    for (int unit = blockIdx.x * 8 + wid; unit < numUnits; unit += ustride) {
        int R0 = unit * 32;
        float c[2][16][4];
        #pragma unroll
        for (int mt = 0; mt < 2; mt++)
            #pragma unroll
            for (int nt = 0; nt < 16; nt++)
                #pragma unroll
                for (int j = 0; j < 4; j++) c[mt][nt][j] = 0.f;

        const float* rp[2][2];
        bool rv[2][2];
        #pragma unroll
        for (int mt = 0; mt < 2; mt++)
            #pragma unroll
            for (int rh = 0; rh < 2; rh++) {
                int r = R0 + mt * 16 + g + 8 * rh;
                rv[mt][rh] = r < N;
                rp[mt][rh] = hin + (size_t)r * 128 + t;
            }

        uint32_t a[2][2][8];
        #pragma unroll
        for (int mt = 0; mt < 2; mt++) {
            #pragma unroll
            for (int q = 0; q < 2; q++) {
                int o = q * 8;
                a[0][mt][q*4+0] = tf32c(rv[mt][0] ? rp[mt][0][o]     : 0.f);
                a[0][mt][q*4+1] = tf32c(rv[mt][1] ? rp[mt][1][o]     : 0.f);
                a[0][mt][q*4+2] = tf32c(rv[mt][0] ? rp[mt][0][o + 4] : 0.f);
                a[0][mt][q*4+3] = tf32c(rv[mt][1] ? rp[mt][1][o + 4] : 0.f);
            }
        }

        #pragma unroll
        for (int kkp = 0; kkp < 8; kkp++) {
            int cur = kkp & 1;
            if (kkp < 7) {
                int kb = (kkp + 1) * 16;
                #pragma unroll
                for (int mt = 0; mt < 2; mt++) {
                    #pragma unroll
                    for (int q = 0; q < 2; q++) {
                        int o = kb + q * 8;
                        a[cur^1][mt][q*4+0] = tf32c(rv[mt][0] ? rp[mt][0][o]     : 0.f);
                        a[cur^1][mt][q*4+1] = tf32c(rv[mt][1] ? rp[mt][1][o]     : 0.f);
                        a[cur^1][mt][q*4+2] = tf32c(rv[mt][0] ? rp[mt][0][o + 4] : 0.f);
                        a[cur^1][mt][q*4+3] = tf32c(rv[mt][1] ? rp[mt][1][o + 4] : 0.f);
                    }
                }
            }
            #pragma unroll
            for (int nt = 0; nt < 16; nt++) {
                uint4 bv = *reinterpret_cast<const uint4*>(
                    sBf + ((nt * 8 + kkp) * 32 + lane) * 4);
                mma8(c[0][nt], a[cur][0][0], a[cur][0][1], a[cur][0][2], a[cur][0][3], bv.x, bv.y);
                mma8(c[0][nt], a[cur][0][4], a[cur][0][5], a[cur][0][6], a[cur][0][7], bv.z, bv.w);
                mma8(c[1][nt], a[cur][1][0], a[cur][1][1], a[cur][1][2], a[cur][1][3], bv.x, bv.y);
                mma8(c[1][nt], a[cur][1][4], a[cur][1][5], a[cur][1][6], a[cur][1][7], bv.z, bv.w);
            }
        }

        // ---- epilogue: bias + ReLU + LN + W2 projection ----
        #pragma unroll
        for (int mt = 0; mt < 2; mt++) {
            #pragma unroll
            for (int rh = 0; rh < 2; rh++) {
                int r = R0 + mt * 16 + g + 8 * rh;
                float s = 0.f;
                #pragma unroll
                for (int nt = 0; nt < 16; nt++) {
                    int col = nt * 8 + 2 * t;
                    float v0 = fmaxf(c[mt][nt][2*rh]   + sBias[col],     0.f);
                    float v1 = fmaxf(c[mt][nt][2*rh+1] + sBias[col + 1], 0.f);
                    c[mt][nt][2*rh]   = v0;
                    c[mt][nt][2*rh+1] = v1;
                    s += v0 + v1;
                }
                s += __shfl_xor_sync(0xffffffffu, s, 1);
                s += __shfl_xor_sync(0xffffffffu, s, 2);
                float mu = s * 0.0078125f;
                float q = 0.f;
                #pragma unroll
                for (int nt = 0; nt < 16; nt++) {
                    c[mt][nt][2*rh]   -= mu;
                    c[mt][nt][2*rh+1] -= mu;
                    q = fmaf(c[mt][nt][2*rh],   c[mt][nt][2*rh],
                        fmaf(c[mt][nt][2*rh+1], c[mt][nt][2*rh+1], q));
                }
                q += __shfl_xor_sync(0xffffffffu, q, 1);
                q += __shfl_xor_sync(0xffffffffu, q, 2);
                float rstd = rsqrtf(q * 0.0078125f + 1e-5f);
                float p0 = 0.f, p1 = 0.f;
                #pragma unroll
                for (int nt = 0; nt < 16; nt++) {
                    int col = nt * 8 + 2 * t;
                    float z0 = c[mt][nt][2*rh]   * rstd * sG[col]     + sB2[col];
                    float z1 = c[mt][nt][2*rh+1] * rstd * sG[col + 1] + sB2[col + 1];
                    p0 = fmaf(z0, sW2[col * 2],     fmaf(z1, sW2[(col + 1) * 2],     p0));
                    p1 = fmaf(z0, sW2[col * 2 + 1], fmaf(z1, sW2[(col + 1) * 2 + 1], p1));
                }
                p0 += __shfl_xor_sync(0xffffffffu, p0, 1);
                p0 += __shfl_xor_sync(0xffffffffu, p0, 2);
                p1 += __shfl_xor_sync(0xffffffffu, p1, 1);
                p1 += __shfl_xor_sync(0xffffffffu, p1, 2);
                if (t == 0 && r < N) {
                    out[(size_t)r * 2 + 0] = p0 + b20;
                    out[(size_t)r * 2 + 1] = p1 + b21;
                }
            }
        }
    }
}

// ---------------------------------------------------------------------------
extern "C" void kernel_launch(void* const* d_in, const int* in_sizes, int n_in,
                              void* d_out, int out_size) {
    const float* features = (const float*)d_in[0];
    const int*   ei       = (const int*)  d_in[1];
    const float* ew       = (const float*)d_in[2];
    const float* Wrel     = (const float*)d_in[3];
    const float* Wroot    = (const float*)d_in[4];
    const float* bias     = (const float*)d_in[5];
    const float* lng      = (const float*)d_in[6];
    const float* lnb      = (const float*)d_in[7];
    const float* alpha    = (const float*)d_in[8];
    const float* W1       = (const float*)d_in[9];
    const float* b1       = (const float*)d_in[10];
    const float* cg       = (const float*)d_in[11];
    const float* cb       = (const float*)d_in[12];
    const float* W2       = (const float*)d_in[13];
    const float* b2       = (const float*)d_in[14];

    int N = in_sizes[0] / DD;
    int E = in_sizes[1] / 2;
    int L = in_sizes[8];

    float *buf0, *buf1, *agg;
    __half *h16;
    int *cnt, *off, *bsum;
    uint4 *epack;
    cudaGetSymbolAddress((void**)&buf0,  g_buf0);
    cudaGetSymbolAddress((void**)&buf1,  g_buf1);
    cudaGetSymbolAddress((void**)&agg,   g_agg);
    cudaGetSymbolAddress((void**)&h16,   g_h16);
    cudaGetSymbolAddress((void**)&cnt,   g_cnt);
    cudaGetSymbolAddress((void**)&off,   g_off);
    cudaGetSymbolAddress((void**)&bsum,  g_bsum);
    cudaGetSymbolAddress((void**)&epack, g_epack);

    int sm = 148;
    cudaDeviceGetAttribute(&sm, cudaDevAttrMultiProcessorCount, 0);

    size_t smemL = 131072;  // 2 x 64 KB
    size_t smemC = 65536;   // 64 KB
    cudaFuncSetAttribute(layer_mma_kernel, cudaFuncAttributeMaxDynamicSharedMemorySize, (int)smemL);
    cudaFuncSetAttribute(cls_mma_kernel,   cudaFuncAttributeMaxDynamicSharedMemorySize, (int)smemC);

    // ---- CSR build (no memsets; cnt self-restores) ----
    int NB = (N + 1023) / 1024;
    hist_kernel <<<(E + 255) / 256, 256>>>(ei, cnt, E);
    scan1_kernel<<<NB, 1024>>>(cnt, off, bsum, N);
    scan2_kernel<<<1, 128>>>(bsum, off, NB, N);
    place_kernel<<<(E + 255) / 256, 256>>>(ei, ew, off, bsum, cnt, epack, E);

    // fp16 mirror of input features
    int n4 = N * DD / 4;
    to_half_kernel<<<(n4 + 255) / 256, 256>>>((const float4*)features, (uint2*)h16, n4);

    int numWarps     = (E + KE - 1) / KE;
    int gatherBlocks = (numWarps + 7) / 8;

    const float* hin = features;
    float* pong[2] = { buf0, buf1 };
    for (int i = 0; i < L; i++) {
        float* hout = pong[i & 1];
        cudaMemsetAsync(agg, 0, (size_t)N * DD * sizeof(float));
        gather_kernel<<<gatherBlocks, 256>>>(h16, epack, agg, E);
        layer_mma_kernel<<<sm, 256, smemL>>>(hin, agg,
                                             Wrel  + (size_t)i * DD * DD,
                                             Wroot + (size_t)i * DD * DD,
                                             bias + i * DD, lng + i * DD, lnb + i * DD,
                                             alpha + i, hout, h16, N);
        hin = hout;
    }
    cls_mma_kernel<<<sm, 256, smemC>>>(hin, W1, b1, cg, cb, W2, b2,
                                       (float*)d_out, N);
}

// round 13
// speedup vs baseline: 2.3731x; 2.3731x over previous
#include <cuda_runtime.h>
#include <cuda_fp16.h>
#include <cstdint>

// ---------------------------------------------------------------------------
// GNN: L x { agg = scatter_add(h[src]*ew, dst); h = PReLU(LN(agg@Wrel + h@Wroot + b)) }
// then logits = LN(relu(h@W1+b1)) @ W2 + b2
// R13: R11 structure (proven 445us) with fp16 m16n8k16 MMA (half the MMA
//      instructions; A still read from fp32 arrays, converted in-register).
// ---------------------------------------------------------------------------

#define MAXN 100000
#define MAXE 1600000
#define DD   128

__device__ float  g_buf0[MAXN * DD];
__device__ float  g_buf1[MAXN * DD];
__device__ float  g_agg [MAXN * DD];
__device__ __half g_h16 [MAXN * DD];
__device__ int    g_cnt [MAXN];       // zero at entry of every call (see place)
__device__ int    g_off [MAXN + 1];
__device__ int    g_bsum[128];
__device__ uint2  g_epack[MAXE];      // {src, weight-bits}

__device__ __forceinline__ uint32_t h2pack(float lo, float hi) {
    __half2 h = __floats2half2_rn(lo, hi);
    return *(uint32_t*)&h;
}
__device__ __forceinline__ void mma16(float c[4], uint32_t a0, uint32_t a1,
                                      uint32_t a2, uint32_t a3,
                                      uint32_t b0, uint32_t b1) {
    asm volatile(
        "mma.sync.aligned.m16n8k16.row.col.f32.f16.f16.f32 "
        "{%0,%1,%2,%3},{%4,%5,%6,%7},{%8,%9},{%0,%1,%2,%3};"
        : "+f"(c[0]), "+f"(c[1]), "+f"(c[2]), "+f"(c[3])
        : "r"(a0), "r"(a1), "r"(a2), "r"(a3), "r"(b0), "r"(b1));
}

// ======================= CSR build (no memsets) ============================
__global__ void hist_kernel(const int* __restrict__ ei, int* __restrict__ cnt, int E) {
    int e = blockIdx.x * blockDim.x + threadIdx.x;
    if (e < E) atomicAdd(cnt + __ldg(ei + E + e), 1);
}
__global__ void scan1_kernel(const int* __restrict__ cnt, int* __restrict__ off,
                             int* __restrict__ bsum, int N) {
    __shared__ int s[1024];
    int tid = threadIdx.x;
    int i = blockIdx.x * 1024 + tid;
    int v = (i < N) ? cnt[i] : 0;
    s[tid] = v; __syncthreads();
    #pragma unroll
    for (int d = 1; d < 1024; d <<= 1) {
        int t = (tid >= d) ? s[tid - d] : 0;
        __syncthreads();
        s[tid] += t;
        __syncthreads();
    }
    if (i < N) off[i] = s[tid] - v;
    if (tid == 1023) bsum[blockIdx.x] = s[1023];
}
__global__ void scan2_kernel(int* __restrict__ bsum, int* __restrict__ off,
                             int NB, int N) {
    __shared__ int s[128];
    int tid = threadIdx.x;
    int v = (tid < NB) ? bsum[tid] : 0;
    s[tid] = v; __syncthreads();
    #pragma unroll
    for (int d = 1; d < 128; d <<= 1) {
        int t = (tid >= d) ? s[tid - d] : 0;
        __syncthreads();
        s[tid] += t;
        __syncthreads();
    }
    if (tid < NB) bsum[tid] = s[tid] - v;
    if (tid == 127) off[N] = s[127];
}
__global__ void place_kernel(const int* __restrict__ ei, const float* __restrict__ ew,
                             const int* __restrict__ off, const int* __restrict__ bsum,
                             int* __restrict__ cursor, uint2* __restrict__ epack, int E) {
    int e = blockIdx.x * blockDim.x + threadIdx.x;
    if (e >= E) return;
    int src = __ldg(ei + e);
    int dst = __ldg(ei + E + e);
    int pos = off[dst] + bsum[dst >> 10] + (atomicSub(cursor + dst, 1) - 1);
    epack[pos] = make_uint2((uint32_t)src, __float_as_uint(__ldg(ew + e)));
}

// ======================= fp32 -> fp16 convert ==============================
__global__ void to_half_kernel(const float4* __restrict__ x,
                               uint2* __restrict__ y, int n4) {
    int i = blockIdx.x * blockDim.x + threadIdx.x;
    if (i >= n4) return;
    float4 v = x[i];
    __half2 a = __floats2half2_rn(v.x, v.y);
    __half2 b = __floats2half2_rn(v.z, v.w);
    y[i] = make_uint2(*(uint32_t*)&a, *(uint32_t*)&b);
}

// ======================= Aggregation: warp per node (R11 proven) ===========
__global__ __launch_bounds__(256)
void gather_kernel(const __half* __restrict__ h16,
                   const int*    __restrict__ off,
                   const int*    __restrict__ bsum,
                   const uint2*  __restrict__ epack,
                   float*        __restrict__ agg, int N) {
    int warp = threadIdx.x >> 5, lane = threadIdx.x & 31;
    int node = blockIdx.x * 8 + warp;
    if (node >= N) return;
    int beg = __ldg(off + node) + __ldg(bsum + (node >> 10));
    int end = (node + 1 == N) ? __ldg(off + N)
                              : __ldg(off + node + 1) + __ldg(bsum + ((node + 1) >> 10));
    float4 acc = {0.f, 0.f, 0.f, 0.f};
    int e = beg;
    for (; e + 3 < end; e += 4) {
        uint2 E0 = __ldg(epack + e);
        uint2 E1 = __ldg(epack + e + 1);
        uint2 E2 = __ldg(epack + e + 2);
        uint2 E3 = __ldg(epack + e + 3);
        uint2 r0 = *reinterpret_cast<const uint2*>(h16 + (size_t)E0.x * DD + lane * 4);
        uint2 r1 = *reinterpret_cast<const uint2*>(h16 + (size_t)E1.x * DD + lane * 4);
        uint2 r2 = *reinterpret_cast<const uint2*>(h16 + (size_t)E2.x * DD + lane * 4);
        uint2 r3 = *reinterpret_cast<const uint2*>(h16 + (size_t)E3.x * DD + lane * 4);
        float w0 = __uint_as_float(E0.y), w1 = __uint_as_float(E1.y);
        float w2 = __uint_as_float(E2.y), w3 = __uint_as_float(E3.y);
        float2 a0 = __half22float2(*(__half2*)&r0.x), b0 = __half22float2(*(__half2*)&r0.y);
        float2 a1 = __half22float2(*(__half2*)&r1.x), b1 = __half22float2(*(__half2*)&r1.y);
        float2 a2 = __half22float2(*(__half2*)&r2.x), b2 = __half22float2(*(__half2*)&r2.y);
        float2 a3 = __half22float2(*(__half2*)&r3.x), b3 = __half22float2(*(__half2*)&r3.y);
        acc.x = fmaf(w0, a0.x, fmaf(w1, a1.x, fmaf(w2, a2.x, fmaf(w3, a3.x, acc.x))));
        acc.y = fmaf(w0, a0.y, fmaf(w1, a1.y, fmaf(w2, a2.y, fmaf(w3, a3.y, acc.y))));
        acc.z = fmaf(w0, b0.x, fmaf(w1, b1.x, fmaf(w2, b2.x, fmaf(w3, b3.x, acc.z))));
        acc.w = fmaf(w0, b0.y, fmaf(w1, b1.y, fmaf(w2, b2.y, fmaf(w3, b3.y, acc.w))));
    }
    for (; e < end; e++) {
        uint2 E0 = __ldg(epack + e);
        float w0 = __uint_as_float(E0.y);
        uint2 r0 = *reinterpret_cast<const uint2*>(h16 + (size_t)E0.x * DD + lane * 4);
        float2 a0 = __half22float2(*(__half2*)&r0.x);
        float2 b0 = __half22float2(*(__half2*)&r0.y);
        acc.x = fmaf(w0, a0.x, acc.x);
        acc.y = fmaf(w0, a0.y, acc.y);
        acc.z = fmaf(w0, b0.x, acc.z);
        acc.w = fmaf(w0, b0.y, acc.w);
    }
    *reinterpret_cast<float4*>(agg + (size_t)node * DD + lane * 4) = acc;
}

// ============== Layer GEMM: warp mma.sync f16 (A from fp32 + cvt) ==========
// Warp unit = 32 rows x 128 cols. B fragments (fp16, R9-verified layout) in
// SMEM: uint2 per (nt,kkp,lane), 32 KB per matrix. A: float2 loads from the
// fp32 arrays, packed to half2 in registers. Double-buffered over kkp.
__global__ __launch_bounds__(256, 1)
void layer_mma_kernel(const float* __restrict__ hin,
                      const float* __restrict__ agg,
                      const float* __restrict__ Wrel,
                      const float* __restrict__ Wroot,
                      const float* __restrict__ bias,
                      const float* __restrict__ lng,
                      const float* __restrict__ lnb,
                      const float* __restrict__ alpha,
                      float*       __restrict__ hout,
                      __half*      __restrict__ hout16,
                      int N) {
    extern __shared__ uint2 smem2[];
    uint2* sBr = smem2;            // 4096 uint2 = 32 KB Wrel fragments
    uint2* sBo = smem2 + 4096;     // 32 KB Wroot fragments
    __shared__ float sBias[128], sG[128], sB2[128];

    int tid = threadIdx.x, wid = tid >> 5, lane = tid & 31;
    int g = lane >> 2, t = lane & 3;

    // ---- stage weights as fp16 B-fragments (layout verified in R9) ----
    // idx -> (nt, kkp, ln): n = nt*8 + (ln>>2), k0 = kkp*16 + 2*(ln&3)
    // b0 = {W[k0][n], W[k0+1][n]}, b1 = {W[k0+8][n], W[k0+9][n]}
    for (int idx = tid; idx < 4096; idx += 256) {
        int nt = idx >> 8, rem = idx & 255, kkp = rem >> 5, ln = rem & 31;
        int gg = ln >> 2, tt = ln & 3;
        int n = nt * 8 + gg, k0 = kkp * 16 + 2 * tt;
        sBr[idx] = make_uint2(
            h2pack(Wrel[(size_t)(k0)     * 128 + n], Wrel[(size_t)(k0 + 1) * 128 + n]),
            h2pack(Wrel[(size_t)(k0 + 8) * 128 + n], Wrel[(size_t)(k0 + 9) * 128 + n]));
        sBo[idx] = make_uint2(
            h2pack(Wroot[(size_t)(k0)     * 128 + n], Wroot[(size_t)(k0 + 1) * 128 + n]),
            h2pack(Wroot[(size_t)(k0 + 8) * 128 + n], Wroot[(size_t)(k0 + 9) * 128 + n]));
    }
    if (tid < 128) {
        sBias[tid] = __ldg(bias + tid);
        sG[tid]    = __ldg(lng + tid);
        sB2[tid]   = __ldg(lnb + tid);
    }
    __syncthreads();

    float al = __ldg(alpha);
    int numUnits = (N + 31) >> 5;
    int ustride  = gridDim.x * 8;

    for (int unit = blockIdx.x * 8 + wid; unit < numUnits; unit += ustride) {
        int R0 = unit * 32;
        float c[2][16][4];
        #pragma unroll
        for (int mt = 0; mt < 2; mt++)
            #pragma unroll
            for (int nt = 0; nt < 16; nt++)
                #pragma unroll
                for (int j = 0; j < 4; j++) c[mt][nt][j] = 0.f;

        #pragma unroll
        for (int half = 0; half < 2; half++) {
            const float* src = half ? hin : agg;
            const uint2* sBf = half ? sBo : sBr;

            // per-lane row pointers at column offset 2t
            const float* rp[2][2];
            bool rv[2][2];
            #pragma unroll
            for (int mt = 0; mt < 2; mt++)
                #pragma unroll
                for (int rh = 0; rh < 2; rh++) {
                    int r = R0 + mt * 16 + g + 8 * rh;
                    rv[mt][rh] = r < N;
                    rp[mt][rh] = src + (size_t)r * 128 + 2 * t;
                }

            // a regs: a0={row g, k 2t..2t+1}, a1={row g+8}, a2={row g, +8}, a3={row g+8, +8}
            uint32_t a[2][2][4];
            #pragma unroll
            for (int mt = 0; mt < 2; mt++) {
                float2 v0 = rv[mt][0] ? *reinterpret_cast<const float2*>(rp[mt][0])     : make_float2(0.f, 0.f);
                float2 v1 = rv[mt][1] ? *reinterpret_cast<const float2*>(rp[mt][1])     : make_float2(0.f, 0.f);
                float2 v2 = rv[mt][0] ? *reinterpret_cast<const float2*>(rp[mt][0] + 8) : make_float2(0.f, 0.f);
                float2 v3 = rv[mt][1] ? *reinterpret_cast<const float2*>(rp[mt][1] + 8) : make_float2(0.f, 0.f);
                a[0][mt][0] = h2pack(v0.x, v0.y);
                a[0][mt][1] = h2pack(v1.x, v1.y);
                a[0][mt][2] = h2pack(v2.x, v2.y);
                a[0][mt][3] = h2pack(v3.x, v3.y);
            }

            #pragma unroll
            for (int kkp = 0; kkp < 8; kkp++) {
                int cur = kkp & 1;
                if (kkp < 7) {
                    int o = (kkp + 1) * 16;
                    #pragma unroll
                    for (int mt = 0; mt < 2; mt++) {
                        float2 v0 = rv[mt][0] ? *reinterpret_cast<const float2*>(rp[mt][0] + o)     : make_float2(0.f, 0.f);
                        float2 v1 = rv[mt][1] ? *reinterpret_cast<const float2*>(rp[mt][1] + o)     : make_float2(0.f, 0.f);
                        float2 v2 = rv[mt][0] ? *reinterpret_cast<const float2*>(rp[mt][0] + o + 8) : make_float2(0.f, 0.f);
                        float2 v3 = rv[mt][1] ? *reinterpret_cast<const float2*>(rp[mt][1] + o + 8) : make_float2(0.f, 0.f);
                        a[cur^1][mt][0] = h2pack(v0.x, v0.y);
                        a[cur^1][mt][1] = h2pack(v1.x, v1.y);
                        a[cur^1][mt][2] = h2pack(v2.x, v2.y);
                        a[cur^1][mt][3] = h2pack(v3.x, v3.y);
                    }
                }
                #pragma unroll
                for (int nt = 0; nt < 16; nt++) {
                    uint2 bv = sBf[(nt << 8) + (kkp << 5) + lane];
                    mma16(c[0][nt], a[cur][0][0], a[cur][0][1], a[cur][0][2], a[cur][0][3], bv.x, bv.y);
                    mma16(c[1][nt], a[cur][1][0], a[cur][1][1], a[cur][1][2], a[cur][1][3], bv.x, bv.y);
                }
            }
        }

        // ---- epilogue: bias + LN + PReLU + fp32/fp16 store ----
        #pragma unroll
        for (int mt = 0; mt < 2; mt++) {
            #pragma unroll
            for (int rh = 0; rh < 2; rh++) {
                int r = R0 + mt * 16 + g + 8 * rh;
                float s = 0.f;
                #pragma unroll
                for (int nt = 0; nt < 16; nt++) {
                    int col = nt * 8 + 2 * t;
                    c[mt][nt][2*rh]   += sBias[col];
                    c[mt][nt][2*rh+1] += sBias[col + 1];
                    s += c[mt][nt][2*rh] + c[mt][nt][2*rh+1];
                }
                s += __shfl_xor_sync(0xffffffffu, s, 1);
                s += __shfl_xor_sync(0xffffffffu, s, 2);
                float mu = s * 0.0078125f;
                float q = 0.f;
                #pragma unroll
                for (int nt = 0; nt < 16; nt++) {
                    c[mt][nt][2*rh]   -= mu;
                    c[mt][nt][2*rh+1] -= mu;
                    q = fmaf(c[mt][nt][2*rh],   c[mt][nt][2*rh],
                        fmaf(c[mt][nt][2*rh+1], c[mt][nt][2*rh+1], q));
                }
                q += __shfl_xor_sync(0xffffffffu, q, 1);
                q += __shfl_xor_sync(0xffffffffu, q, 2);
                float rstd = rsqrtf(q * 0.0078125f + 1e-5f);
                if (r < N) {
                    #pragma unroll
                    for (int nt = 0; nt < 16; nt++) {
                        int col = nt * 8 + 2 * t;
                        float y0 = c[mt][nt][2*rh]   * rstd * sG[col]     + sB2[col];
                        float y1 = c[mt][nt][2*rh+1] * rstd * sG[col + 1] + sB2[col + 1];
                        y0 = y0 >= 0.f ? y0 : al * y0;
                        y1 = y1 >= 0.f ? y1 : al * y1;
                        *reinterpret_cast<float2*>(hout + (size_t)r * 128 + col) =
                            make_float2(y0, y1);
                        *reinterpret_cast<__half2*>(hout16 + (size_t)r * 128 + col) =
                            __floats2half2_rn(y0, y1);
                    }
                }
            }
        }
    }
}

// ============== Classifier: warp mma.sync f16 ==============================
__global__ __launch_bounds__(256, 1)
void cls_mma_kernel(const float* __restrict__ hin,
                    const float* __restrict__ W1,
                    const float* __restrict__ b1,
                    const float* __restrict__ lng,
                    const float* __restrict__ lnb,
                    const float* __restrict__ W2,
                    const float* __restrict__ b2,
                    float*       __restrict__ out,
                    int N) {
    extern __shared__ uint2 smem2[];
    uint2* sBf = smem2;            // 32 KB W1 fragments
    __shared__ float sBias[128], sG[128], sB2[128], sW2[256];

    int tid = threadIdx.x, wid = tid >> 5, lane = tid & 31;
    int g = lane >> 2, t = lane & 3;

    for (int idx = tid; idx < 4096; idx += 256) {
        int nt = idx >> 8, rem = idx & 255, kkp = rem >> 5, ln = rem & 31;
        int gg = ln >> 2, tt = ln & 3;
        int n = nt * 8 + gg, k0 = kkp * 16 + 2 * tt;
        sBf[idx] = make_uint2(
            h2pack(W1[(size_t)(k0)     * 128 + n], W1[(size_t)(k0 + 1) * 128 + n]),
            h2pack(W1[(size_t)(k0 + 8) * 128 + n], W1[(size_t)(k0 + 9) * 128 + n]));
    }
    if (tid < 128) {
        sBias[tid] = __ldg(b1 + tid);
        sG[tid]    = __ldg(lng + tid);
        sB2[tid]   = __ldg(lnb + tid);
        sW2[tid * 2]     = __ldg(W2 + tid * 2);
        sW2[tid * 2 + 1] = __ldg(W2 + tid * 2 + 1);
    }
    __syncthreads();

    float b20 = __ldg(b2 + 0), b21 = __ldg(b2 + 1);
    int numUnits = (N + 31) >> 5;
    int ustride  = gridDim.x * 8;

    for (int unit = blockIdx.x * 8 + wid; unit < numUnits; unit += ustride) {
        int R0 = unit * 32;
        float c[2][16][4];
        #pragma unroll
        for (int mt = 0; mt < 2; mt++)
            #pragma unroll
            for (int nt = 0; nt < 16; nt++)
                #pragma unroll
                for (int j = 0; j < 4; j++) c[mt][nt][j] = 0.f;

        const float* rp[2][2];
        bool rv[2][2];
        #pragma unroll
        for (int mt = 0; mt < 2; mt++)
            #pragma unroll
            for (int rh = 0; rh < 2; rh++) {
                int r = R0 + mt * 16 + g + 8 * rh;
                rv[mt][rh] = r < N;
                rp[mt][rh] = hin + (size_t)r * 128 + 2 * t;
            }

        uint32_t a[2][2][4];
        #pragma unroll
        for (int mt = 0; mt < 2; mt++) {
            float2 v0 = rv[mt][0] ? *reinterpret_cast<const float2*>(rp[mt][0])     : make_float2(0.f, 0.f);
            float2 v1 = rv[mt][1] ? *reinterpret_cast<const float2*>(rp[mt][1])     : make_float2(0.f, 0.f);
            float2 v2 = rv[mt][0] ? *reinterpret_cast<const float2*>(rp[mt][0] + 8) : make_float2(0.f, 0.f);
            float2 v3 = rv[mt][1] ? *reinterpret_cast<const float2*>(rp[mt][1] + 8) : make_float2(0.f, 0.f);
            a[0][mt][0] = h2pack(v0.x, v0.y);
            a[0][mt][1] = h2pack(v1.x, v1.y);
            a[0][mt][2] = h2pack(v2.x, v2.y);
            a[0][mt][3] = h2pack(v3.x, v3.y);
        }

        #pragma unroll
        for (int kkp = 0; kkp < 8; kkp++) {
            int cur = kkp & 1;
            if (kkp < 7) {
                int o = (kkp + 1) * 16;
                #pragma unroll
                for (int mt = 0; mt < 2; mt++) {
                    float2 v0 = rv[mt][0] ? *reinterpret_cast<const float2*>(rp[mt][0] + o)     : make_float2(0.f, 0.f);
                    float2 v1 = rv[mt][1] ? *reinterpret_cast<const float2*>(rp[mt][1] + o)     : make_float2(0.f, 0.f);
                    float2 v2 = rv[mt][0] ? *reinterpret_cast<const float2*>(rp[mt][0] + o + 8) : make_float2(0.f, 0.f);
                    float2 v3 = rv[mt][1] ? *reinterpret_cast<const float2*>(rp[mt][1] + o + 8) : make_float2(0.f, 0.f);
                    a[cur^1][mt][0] = h2pack(v0.x, v0.y);
                    a[cur^1][mt][1] = h2pack(v1.x, v1.y);
                    a[cur^1][mt][2] = h2pack(v2.x, v2.y);
                    a[cur^1][mt][3] = h2pack(v3.x, v3.y);
                }
            }
            #pragma unroll
            for (int nt = 0; nt < 16; nt++) {
                uint2 bv = sBf[(nt << 8) + (kkp << 5) + lane];
                mma16(c[0][nt], a[cur][0][0], a[cur][0][1], a[cur][0][2], a[cur][0][3], bv.x, bv.y);
                mma16(c[1][nt], a[cur][1][0], a[cur][1][1], a[cur][1][2], a[cur][1][3], bv.x, bv.y);
            }
        }

        // ---- epilogue: bias + ReLU + LN + W2 projection ----
        #pragma unroll
        for (int mt = 0; mt < 2; mt++) {
            #pragma unroll
            for (int rh = 0; rh < 2; rh++) {
                int r = R0 + mt * 16 + g + 8 * rh;
                float s = 0.f;
                #pragma unroll
                for (int nt = 0; nt < 16; nt++) {
                    int col = nt * 8 + 2 * t;
                    float v0 = fmaxf(c[mt][nt][2*rh]   + sBias[col],     0.f);
                    float v1 = fmaxf(c[mt][nt][2*rh+1] + sBias[col + 1], 0.f);
                    c[mt][nt][2*rh]   = v0;
                    c[mt][nt][2*rh+1] = v1;
                    s += v0 + v1;
                }
                s += __shfl_xor_sync(0xffffffffu, s, 1);
                s += __shfl_xor_sync(0xffffffffu, s, 2);
                float mu = s * 0.0078125f;
                float q = 0.f;
                #pragma unroll
                for (int nt = 0; nt < 16; nt++) {
                    c[mt][nt][2*rh]   -= mu;
                    c[mt][nt][2*rh+1] -= mu;
                    q = fmaf(c[mt][nt][2*rh],   c[mt][nt][2*rh],
                        fmaf(c[mt][nt][2*rh+1], c[mt][nt][2*rh+1], q));
                }
                q += __shfl_xor_sync(0xffffffffu, q, 1);
                q += __shfl_xor_sync(0xffffffffu, q, 2);
                float rstd = rsqrtf(q * 0.0078125f + 1e-5f);
                float p0 = 0.f, p1 = 0.f;
                #pragma unroll
                for (int nt = 0; nt < 16; nt++) {
                    int col = nt * 8 + 2 * t;
                    float z0 = c[mt][nt][2*rh]   * rstd * sG[col]     + sB2[col];
                    float z1 = c[mt][nt][2*rh+1] * rstd * sG[col + 1] + sB2[col + 1];
                    p0 = fmaf(z0, sW2[col * 2],     fmaf(z1, sW2[(col + 1) * 2],     p0));
                    p1 = fmaf(z0, sW2[col * 2 + 1], fmaf(z1, sW2[(col + 1) * 2 + 1], p1));
                }
                p0 += __shfl_xor_sync(0xffffffffu, p0, 1);
                p0 += __shfl_xor_sync(0xffffffffu, p0, 2);
                p1 += __shfl_xor_sync(0xffffffffu, p1, 1);
                p1 += __shfl_xor_sync(0xffffffffu, p1, 2);
                if (t == 0 && r < N) {
                    out[(size_t)r * 2 + 0] = p0 + b20;
                    out[(size_t)r * 2 + 1] = p1 + b21;
                }
            }
        }
    }
}

// ---------------------------------------------------------------------------
extern "C" void kernel_launch(void* const* d_in, const int* in_sizes, int n_in,
                              void* d_out, int out_size) {
    const float* features = (const float*)d_in[0];
    const int*   ei       = (const int*)  d_in[1];
    const float* ew       = (const float*)d_in[2];
    const float* Wrel     = (const float*)d_in[3];
    const float* Wroot    = (const float*)d_in[4];
    const float* bias     = (const float*)d_in[5];
    const float* lng      = (const float*)d_in[6];
    const float* lnb      = (const float*)d_in[7];
    const float* alpha    = (const float*)d_in[8];
    const float* W1       = (const float*)d_in[9];
    const float* b1       = (const float*)d_in[10];
    const float* cg       = (const float*)d_in[11];
    const float* cb       = (const float*)d_in[12];
    const float* W2       = (const float*)d_in[13];
    const float* b2       = (const float*)d_in[14];

    int N = in_sizes[0] / DD;
    int E = in_sizes[1] / 2;
    int L = in_sizes[8];

    float *buf0, *buf1, *agg;
    __half *h16;
    int *cnt, *off, *bsum;
    uint2 *epack;
    cudaGetSymbolAddress((void**)&buf0,  g_buf0);
    cudaGetSymbolAddress((void**)&buf1,  g_buf1);
    cudaGetSymbolAddress((void**)&agg,   g_agg);
    cudaGetSymbolAddress((void**)&h16,   g_h16);
    cudaGetSymbolAddress((void**)&cnt,   g_cnt);
    cudaGetSymbolAddress((void**)&off,   g_off);
    cudaGetSymbolAddress((void**)&bsum,  g_bsum);
    cudaGetSymbolAddress((void**)&epack, g_epack);

    int sm = 148;
    cudaDeviceGetAttribute(&sm, cudaDevAttrMultiProcessorCount, 0);

    size_t smemL = 65536;   // 2 x 32 KB fp16 B fragments
    size_t smemC = 32768;   // 32 KB
    cudaFuncSetAttribute(layer_mma_kernel, cudaFuncAttributeMaxDynamicSharedMemorySize, (int)smemL);
    cudaFuncSetAttribute(cls_mma_kernel,   cudaFuncAttributeMaxDynamicSharedMemorySize, (int)smemC);

    // ---- CSR build (no memsets; cnt self-restores) ----
    int NB = (N + 1023) / 1024;
    hist_kernel <<<(E + 255) / 256, 256>>>(ei, cnt, E);
    scan1_kernel<<<NB, 1024>>>(cnt, off, bsum, N);
    scan2_kernel<<<1, 128>>>(bsum, off, NB, N);
    place_kernel<<<(E + 255) / 256, 256>>>(ei, ew, off, bsum, cnt, epack, E);

    // fp16 mirror of input features
    int n4 = N * DD / 4;
    to_half_kernel<<<(n4 + 255) / 256, 256>>>((const float4*)features, (uint2*)h16, n4);

    int gatherBlocks = (N + 7) / 8;

    const float* hin = features;
    float* pong[2] = { buf0, buf1 };
    for (int i = 0; i < L; i++) {
        float* hout = pong[i & 1];
        gather_kernel<<<gatherBlocks, 256>>>(h16, off, bsum, epack, agg, N);
        layer_mma_kernel<<<sm, 256, smemL>>>(hin, agg,
                                             Wrel  + (size_t)i * DD * DD,
                                             Wroot + (size_t)i * DD * DD,
                                             bias + i * DD, lng + i * DD, lnb + i * DD,
                                             alpha + i, hout, h16, N);
        hin = hout;
    }
    cls_mma_kernel<<<sm, 256, smemC>>>(hin, W1, b1, cg, cb, W2, b2,
                                       (float*)d_out, N);
}

// round 14
// speedup vs baseline: 2.7190x; 1.1458x over previous
#include <cuda_runtime.h>
#include <cuda_fp16.h>
#include <cstdint>

// ---------------------------------------------------------------------------
// GNN: L x { agg = scatter_add(h[src]*ew, dst); h = PReLU(LN(agg@Wrel + h@Wroot + b)) }
// then logits = LN(relu(h@W1+b1)) @ W2 + b2
// R14: R13 kernel skeleton (fp16 m16n8k16 MMA, occ-1) with fp16-ONLY storage
//      for h and agg (halves layer-kernel traffic; dataflow proven in R9).
// ---------------------------------------------------------------------------

#define MAXN 100000
#define MAXE 1600000
#define DD   128

__device__ __half g_h16a [MAXN * DD];
__device__ __half g_h16b [MAXN * DD];
__device__ __half g_agg16[MAXN * DD];
__device__ int    g_cnt [MAXN];       // zero at entry of every call (see place)
__device__ int    g_off [MAXN + 1];
__device__ int    g_bsum[128];
__device__ uint2  g_epack[MAXE];      // {src, weight-bits}

__device__ __forceinline__ uint32_t h2pack(float lo, float hi) {
    __half2 h = __floats2half2_rn(lo, hi);
    return *(uint32_t*)&h;
}
__device__ __forceinline__ void mma16(float c[4], uint32_t a0, uint32_t a1,
                                      uint32_t a2, uint32_t a3,
                                      uint32_t b0, uint32_t b1) {
    asm volatile(
        "mma.sync.aligned.m16n8k16.row.col.f32.f16.f16.f32 "
        "{%0,%1,%2,%3},{%4,%5,%6,%7},{%8,%9},{%0,%1,%2,%3};"
        : "+f"(c[0]), "+f"(c[1]), "+f"(c[2]), "+f"(c[3])
        : "r"(a0), "r"(a1), "r"(a2), "r"(a3), "r"(b0), "r"(b1));
}

// ======================= CSR build (no memsets) ============================
__global__ void hist_kernel(const int* __restrict__ ei, int* __restrict__ cnt, int E) {
    int e = blockIdx.x * blockDim.x + threadIdx.x;
    if (e < E) atomicAdd(cnt + __ldg(ei + E + e), 1);
}
__global__ void scan1_kernel(const int* __restrict__ cnt, int* __restrict__ off,
                             int* __restrict__ bsum, int N) {
    __shared__ int s[1024];
    int tid = threadIdx.x;
    int i = blockIdx.x * 1024 + tid;
    int v = (i < N) ? cnt[i] : 0;
    s[tid] = v; __syncthreads();
    #pragma unroll
    for (int d = 1; d < 1024; d <<= 1) {
        int t = (tid >= d) ? s[tid - d] : 0;
        __syncthreads();
        s[tid] += t;
        __syncthreads();
    }
    if (i < N) off[i] = s[tid] - v;
    if (tid == 1023) bsum[blockIdx.x] = s[1023];
}
__global__ void scan2_kernel(int* __restrict__ bsum, int* __restrict__ off,
                             int NB, int N) {
    __shared__ int s[128];
    int tid = threadIdx.x;
    int v = (tid < NB) ? bsum[tid] : 0;
    s[tid] = v; __syncthreads();
    #pragma unroll
    for (int d = 1; d < 128; d <<= 1) {
        int t = (tid >= d) ? s[tid - d] : 0;
        __syncthreads();
        s[tid] += t;
        __syncthreads();
    }
    if (tid < NB) bsum[tid] = s[tid] - v;
    if (tid == 127) off[N] = s[127];
}
__global__ void place_kernel(const int* __restrict__ ei, const float* __restrict__ ew,
                             const int* __restrict__ off, const int* __restrict__ bsum,
                             int* __restrict__ cursor, uint2* __restrict__ epack, int E) {
    int e = blockIdx.x * blockDim.x + threadIdx.x;
    if (e >= E) return;
    int src = __ldg(ei + e);
    int dst = __ldg(ei + E + e);
    int pos = off[dst] + bsum[dst >> 10] + (atomicSub(cursor + dst, 1) - 1);
    epack[pos] = make_uint2((uint32_t)src, __float_as_uint(__ldg(ew + e)));
}

// ======================= fp32 -> fp16 convert ==============================
__global__ void to_half_kernel(const float4* __restrict__ x,
                               uint2* __restrict__ y, int n4) {
    int i = blockIdx.x * blockDim.x + threadIdx.x;
    if (i >= n4) return;
    float4 v = x[i];
    __half2 a = __floats2half2_rn(v.x, v.y);
    __half2 b = __floats2half2_rn(v.z, v.w);
    y[i] = make_uint2(*(uint32_t*)&a, *(uint32_t*)&b);
}

// ======================= Aggregation: warp per node (R11 loop) =============
__global__ __launch_bounds__(256)
void gather_kernel(const __half* __restrict__ h16,
                   const int*    __restrict__ off,
                   const int*    __restrict__ bsum,
                   const uint2*  __restrict__ epack,
                   __half*       __restrict__ agg16, int N) {
    int warp = threadIdx.x >> 5, lane = threadIdx.x & 31;
    int node = blockIdx.x * 8 + warp;
    if (node >= N) return;
    int beg = __ldg(off + node) + __ldg(bsum + (node >> 10));
    int end = (node + 1 == N) ? __ldg(off + N)
                              : __ldg(off + node + 1) + __ldg(bsum + ((node + 1) >> 10));
    float4 acc = {0.f, 0.f, 0.f, 0.f};
    int e = beg;
    for (; e + 3 < end; e += 4) {
        uint2 E0 = __ldg(epack + e);
        uint2 E1 = __ldg(epack + e + 1);
        uint2 E2 = __ldg(epack + e + 2);
        uint2 E3 = __ldg(epack + e + 3);
        uint2 r0 = *reinterpret_cast<const uint2*>(h16 + (size_t)E0.x * DD + lane * 4);
        uint2 r1 = *reinterpret_cast<const uint2*>(h16 + (size_t)E1.x * DD + lane * 4);
        uint2 r2 = *reinterpret_cast<const uint2*>(h16 + (size_t)E2.x * DD + lane * 4);
        uint2 r3 = *reinterpret_cast<const uint2*>(h16 + (size_t)E3.x * DD + lane * 4);
        float w0 = __uint_as_float(E0.y), w1 = __uint_as_float(E1.y);
        float w2 = __uint_as_float(E2.y), w3 = __uint_as_float(E3.y);
        float2 a0 = __half22float2(*(__half2*)&r0.x), b0 = __half22float2(*(__half2*)&r0.y);
        float2 a1 = __half22float2(*(__half2*)&r1.x), b1 = __half22float2(*(__half2*)&r1.y);
        float2 a2 = __half22float2(*(__half2*)&r2.x), b2 = __half22float2(*(__half2*)&r2.y);
        float2 a3 = __half22float2(*(__half2*)&r3.x), b3 = __half22float2(*(__half2*)&r3.y);
        acc.x = fmaf(w0, a0.x, fmaf(w1, a1.x, fmaf(w2, a2.x, fmaf(w3, a3.x, acc.x))));
        acc.y = fmaf(w0, a0.y, fmaf(w1, a1.y, fmaf(w2, a2.y, fmaf(w3, a3.y, acc.y))));
        acc.z = fmaf(w0, b0.x, fmaf(w1, b1.x, fmaf(w2, b2.x, fmaf(w3, b3.x, acc.z))));
        acc.w = fmaf(w0, b0.y, fmaf(w1, b1.y, fmaf(w2, b2.y, fmaf(w3, b3.y, acc.w))));
    }
    for (; e < end; e++) {
        uint2 E0 = __ldg(epack + e);
        float w0 = __uint_as_float(E0.y);
        uint2 r0 = *reinterpret_cast<const uint2*>(h16 + (size_t)E0.x * DD + lane * 4);
        float2 a0 = __half22float2(*(__half2*)&r0.x);
        float2 b0 = __half22float2(*(__half2*)&r0.y);
        acc.x = fmaf(w0, a0.x, acc.x);
        acc.y = fmaf(w0, a0.y, acc.y);
        acc.z = fmaf(w0, b0.x, acc.z);
        acc.w = fmaf(w0, b0.y, acc.w);
    }
    *reinterpret_cast<uint2*>(agg16 + (size_t)node * DD + lane * 4) =
        make_uint2(h2pack(acc.x, acc.y), h2pack(acc.z, acc.w));
}

// ============== Layer GEMM: warp mma.sync f16, A from fp16 arrays ==========
// Warp unit = 32 rows x 128 cols. B fragments (fp16) in SMEM, 32 KB each.
// A regs are direct uint32 loads (cols 2t,2t+1 / +8) -- no conversion.
__global__ __launch_bounds__(256, 1)
void layer_mma_kernel(const __half* __restrict__ hin16,
                      const __half* __restrict__ agg16,
                      const float* __restrict__ Wrel,
                      const float* __restrict__ Wroot,
                      const float* __restrict__ bias,
                      const float* __restrict__ lng,
                      const float* __restrict__ lnb,
                      const float* __restrict__ alpha,
                      __half*      __restrict__ hout16,
                      int N) {
    extern __shared__ uint2 smem2[];
    uint2* sBr = smem2;            // 4096 uint2 = 32 KB Wrel fragments
    uint2* sBo = smem2 + 4096;     // 32 KB Wroot fragments
    __shared__ float sBias[128], sG[128], sB2[128];

    int tid = threadIdx.x, wid = tid >> 5, lane = tid & 31;
    int g = lane >> 2, t = lane & 3;

    for (int idx = tid; idx < 4096; idx += 256) {
        int nt = idx >> 8, rem = idx & 255, kkp = rem >> 5, ln = rem & 31;
        int gg = ln >> 2, tt = ln & 3;
        int n = nt * 8 + gg, k0 = kkp * 16 + 2 * tt;
        sBr[idx] = make_uint2(
            h2pack(Wrel[(size_t)(k0)     * 128 + n], Wrel[(size_t)(k0 + 1) * 128 + n]),
            h2pack(Wrel[(size_t)(k0 + 8) * 128 + n], Wrel[(size_t)(k0 + 9) * 128 + n]));
        sBo[idx] = make_uint2(
            h2pack(Wroot[(size_t)(k0)     * 128 + n], Wroot[(size_t)(k0 + 1) * 128 + n]),
            h2pack(Wroot[(size_t)(k0 + 8) * 128 + n], Wroot[(size_t)(k0 + 9) * 128 + n]));
    }
    if (tid < 128) {
        sBias[tid] = __ldg(bias + tid);
        sG[tid]    = __ldg(lng + tid);
        sB2[tid]   = __ldg(lnb + tid);
    }
    __syncthreads();

    float al = __ldg(alpha);
    int numUnits = (N + 31) >> 5;
    int ustride  = gridDim.x * 8;

    for (int unit = blockIdx.x * 8 + wid; unit < numUnits; unit += ustride) {
        int R0 = unit * 32;
        float c[2][16][4];
        #pragma unroll
        for (int mt = 0; mt < 2; mt++)
            #pragma unroll
            for (int nt = 0; nt < 16; nt++)
                #pragma unroll
                for (int j = 0; j < 4; j++) c[mt][nt][j] = 0.f;

        #pragma unroll
        for (int half = 0; half < 2; half++) {
            const __half* src = half ? hin16 : agg16;
            const uint2*  sBf = half ? sBo : sBr;

            const __half* rp[2][2];
            bool rv[2][2];
            #pragma unroll
            for (int mt = 0; mt < 2; mt++)
                #pragma unroll
                for (int rh = 0; rh < 2; rh++) {
                    int r = R0 + mt * 16 + g + 8 * rh;
                    rv[mt][rh] = r < N;
                    rp[mt][rh] = src + (size_t)r * 128 + 2 * t;
                }

            uint32_t a[2][2][4];
            #pragma unroll
            for (int mt = 0; mt < 2; mt++) {
                a[0][mt][0] = rv[mt][0] ? *(const uint32_t*)(rp[mt][0])     : 0u;
                a[0][mt][1] = rv[mt][1] ? *(const uint32_t*)(rp[mt][1])     : 0u;
                a[0][mt][2] = rv[mt][0] ? *(const uint32_t*)(rp[mt][0] + 8) : 0u;
                a[0][mt][3] = rv[mt][1] ? *(const uint32_t*)(rp[mt][1] + 8) : 0u;
            }

            #pragma unroll
            for (int kkp = 0; kkp < 8; kkp++) {
                int cur = kkp & 1;
                if (kkp < 7) {
                    int o = (kkp + 1) * 16;
                    #pragma unroll
                    for (int mt = 0; mt < 2; mt++) {
                        a[cur^1][mt][0] = rv[mt][0] ? *(const uint32_t*)(rp[mt][0] + o)     : 0u;
                        a[cur^1][mt][1] = rv[mt][1] ? *(const uint32_t*)(rp[mt][1] + o)     : 0u;
                        a[cur^1][mt][2] = rv[mt][0] ? *(const uint32_t*)(rp[mt][0] + o + 8) : 0u;
                        a[cur^1][mt][3] = rv[mt][1] ? *(const uint32_t*)(rp[mt][1] + o + 8) : 0u;
                    }
                }
                #pragma unroll
                for (int nt = 0; nt < 16; nt++) {
                    uint2 bv = sBf[(nt << 8) + (kkp << 5) + lane];
                    mma16(c[0][nt], a[cur][0][0], a[cur][0][1], a[cur][0][2], a[cur][0][3], bv.x, bv.y);
                    mma16(c[1][nt], a[cur][1][0], a[cur][1][1], a[cur][1][2], a[cur][1][3], bv.x, bv.y);
                }
            }
        }

        // ---- epilogue: bias + LN + PReLU + fp16 store ----
        #pragma unroll
        for (int mt = 0; mt < 2; mt++) {
            #pragma unroll
            for (int rh = 0; rh < 2; rh++) {
                int r = R0 + mt * 16 + g + 8 * rh;
                float s = 0.f;
                #pragma unroll
                for (int nt = 0; nt < 16; nt++) {
                    int col = nt * 8 + 2 * t;
                    c[mt][nt][2*rh]   += sBias[col];
                    c[mt][nt][2*rh+1] += sBias[col + 1];
                    s += c[mt][nt][2*rh] + c[mt][nt][2*rh+1];
                }
                s += __shfl_xor_sync(0xffffffffu, s, 1);
                s += __shfl_xor_sync(0xffffffffu, s, 2);
                float mu = s * 0.0078125f;
                float q = 0.f;
                #pragma unroll
                for (int nt = 0; nt < 16; nt++) {
                    c[mt][nt][2*rh]   -= mu;
                    c[mt][nt][2*rh+1] -= mu;
                    q = fmaf(c[mt][nt][2*rh],   c[mt][nt][2*rh],
                        fmaf(c[mt][nt][2*rh+1], c[mt][nt][2*rh+1], q));
                }
                q += __shfl_xor_sync(0xffffffffu, q, 1);
                q += __shfl_xor_sync(0xffffffffu, q, 2);
                float rstd = rsqrtf(q * 0.0078125f + 1e-5f);
                if (r < N) {
                    #pragma unroll
                    for (int nt = 0; nt < 16; nt++) {
                        int col = nt * 8 + 2 * t;
                        float y0 = c[mt][nt][2*rh]   * rstd * sG[col]     + sB2[col];
                        float y1 = c[mt][nt][2*rh+1] * rstd * sG[col + 1] + sB2[col + 1];
                        y0 = y0 >= 0.f ? y0 : al * y0;
                        y1 = y1 >= 0.f ? y1 : al * y1;
                        *reinterpret_cast<__half2*>(hout16 + (size_t)r * 128 + col) =
                            __floats2half2_rn(y0, y1);
                    }
                }
            }
        }
    }
}

// ============== Classifier: warp mma.sync f16, A from fp16 =================
__global__ __launch_bounds__(256, 1)
void cls_mma_kernel(const __half* __restrict__ hin16,
                    const float* __restrict__ W1,
                    const float* __restrict__ b1,
                    const float* __restrict__ lng,
                    const float* __restrict__ lnb,
                    const float* __restrict__ W2,
                    const float* __restrict__ b2,
                    float*       __restrict__ out,
                    int N) {
    extern __shared__ uint2 smem2[];
    uint2* sBf = smem2;            // 32 KB W1 fragments
    __shared__ float sBias[128], sG[128], sB2[128], sW2[256];

    int tid = threadIdx.x, wid = tid >> 5, lane = tid & 31;
    int g = lane >> 2, t = lane & 3;

    for (int idx = tid; idx < 4096; idx += 256) {
        int nt = idx >> 8, rem = idx & 255, kkp = rem >> 5, ln = rem & 31;
        int gg = ln >> 2, tt = ln & 3;
        int n = nt * 8 + gg, k0 = kkp * 16 + 2 * tt;
        sBf[idx] = make_uint2(
            h2pack(W1[(size_t)(k0)     * 128 + n], W1[(size_t)(k0 + 1) * 128 + n]),
            h2pack(W1[(size_t)(k0 + 8) * 128 + n], W1[(size_t)(k0 + 9) * 128 + n]));
    }
    if (tid < 128) {
        sBias[tid] = __ldg(b1 + tid);
        sG[tid]    = __ldg(lng + tid);
        sB2[tid]   = __ldg(lnb + tid);
        sW2[tid * 2]     = __ldg(W2 + tid * 2);
        sW2[tid * 2 + 1] = __ldg(W2 + tid * 2 + 1);
    }
    __syncthreads();

    float b20 = __ldg(b2 + 0), b21 = __ldg(b2 + 1);
    int numUnits = (N + 31) >> 5;
    int ustride  = gridDim.x * 8;

    for (int unit = blockIdx.x * 8 + wid; unit < numUnits; unit += ustride) {
        int R0 = unit * 32;
        float c[2][16][4];
        #pragma unroll
        for (int mt = 0; mt < 2; mt++)
            #pragma unroll
            for (int nt = 0; nt < 16; nt++)
                #pragma unroll
                for (int j = 0; j < 4; j++) c[mt][nt][j] = 0.f;

        const __half* rp[2][2];
        bool rv[2][2];
        #pragma unroll
        for (int mt = 0; mt < 2; mt++)
            #pragma unroll
            for (int rh = 0; rh < 2; rh++) {
                int r = R0 + mt * 16 + g + 8 * rh;
                rv[mt][rh] = r < N;
                rp[mt][rh] = hin16 + (size_t)r * 128 + 2 * t;
            }

        uint32_t a[2][2][4];
        #pragma unroll
        for (int mt = 0; mt < 2; mt++) {
            a[0][mt][0] = rv[mt][0] ? *(const uint32_t*)(rp[mt][0])     : 0u;
            a[0][mt][1] = rv[mt][1] ? *(const uint32_t*)(rp[mt][1])     : 0u;
            a[0][mt][2] = rv[mt][0] ? *(const uint32_t*)(rp[mt][0] + 8) : 0u;
            a[0][mt][3] = rv[mt][1] ? *(const uint32_t*)(rp[mt][1] + 8) : 0u;
        }

        #pragma unroll
        for (int kkp = 0; kkp < 8; kkp++) {
            int cur = kkp & 1;
            if (kkp < 7) {
                int o = (kkp + 1) * 16;
                #pragma unroll
                for (int mt = 0; mt < 2; mt++) {
                    a[cur^1][mt][0] = rv[mt][0] ? *(const uint32_t*)(rp[mt][0] + o)     : 0u;
                    a[cur^1][mt][1] = rv[mt][1] ? *(const uint32_t*)(rp[mt][1] + o)     : 0u;
                    a[cur^1][mt][2] = rv[mt][0] ? *(const uint32_t*)(rp[mt][0] + o + 8) : 0u;
                    a[cur^1][mt][3] = rv[mt][1] ? *(const uint32_t*)(rp[mt][1] + o + 8) : 0u;
                }
            }
            #pragma unroll
            for (int nt = 0; nt < 16; nt++) {
                uint2 bv = sBf[(nt << 8) + (kkp << 5) + lane];
                mma16(c[0][nt], a[cur][0][0], a[cur][0][1], a[cur][0][2], a[cur][0][3], bv.x, bv.y);
                mma16(c[1][nt], a[cur][1][0], a[cur][1][1], a[cur][1][2], a[cur][1][3], bv.x, bv.y);
            }
        }

        // ---- epilogue: bias + ReLU + LN + W2 projection ----
        #pragma unroll
        for (int mt = 0; mt < 2; mt++) {
            #pragma unroll
            for (int rh = 0; rh < 2; rh++) {
                int r = R0 + mt * 16 + g + 8 * rh;
                float s = 0.f;
                #pragma unroll
                for (int nt = 0; nt < 16; nt++) {
                    int col = nt * 8 + 2 * t;
                    float v0 = fmaxf(c[mt][nt][2*rh]   + sBias[col],     0.f);
                    float v1 = fmaxf(c[mt][nt][2*rh+1] + sBias[col + 1], 0.f);
                    c[mt][nt][2*rh]   = v0;
                    c[mt][nt][2*rh+1] = v1;
                    s += v0 + v1;
                }
                s += __shfl_xor_sync(0xffffffffu, s, 1);
                s += __shfl_xor_sync(0xffffffffu, s, 2);
                float mu = s * 0.0078125f;
                float q = 0.f;
                #pragma unroll
                for (int nt = 0; nt < 16; nt++) {
                    c[mt][nt][2*rh]   -= mu;
                    c[mt][nt][2*rh+1] -= mu;
                    q = fmaf(c[mt][nt][2*rh],   c[mt][nt][2*rh],
                        fmaf(c[mt][nt][2*rh+1], c[mt][nt][2*rh+1], q));
                }
                q += __shfl_xor_sync(0xffffffffu, q, 1);
                q += __shfl_xor_sync(0xffffffffu, q, 2);
                float rstd = rsqrtf(q * 0.0078125f + 1e-5f);
                float p0 = 0.f, p1 = 0.f;
                #pragma unroll
                for (int nt = 0; nt < 16; nt++) {
                    int col = nt * 8 + 2 * t;
                    float z0 = c[mt][nt][2*rh]   * rstd * sG[col]     + sB2[col];
                    float z1 = c[mt][nt][2*rh+1] * rstd * sG[col + 1] + sB2[col + 1];
                    p0 = fmaf(z0, sW2[col * 2],     fmaf(z1, sW2[(col + 1) * 2],     p0));
                    p1 = fmaf(z0, sW2[col * 2 + 1], fmaf(z1, sW2[(col + 1) * 2 + 1], p1));
                }
                p0 += __shfl_xor_sync(0xffffffffu, p0, 1);
                p0 += __shfl_xor_sync(0xffffffffu, p0, 2);
                p1 += __shfl_xor_sync(0xffffffffu, p1, 1);
                p1 += __shfl_xor_sync(0xffffffffu, p1, 2);
                if (t == 0 && r < N) {
                    out[(size_t)r * 2 + 0] = p0 + b20;
                    out[(size_t)r * 2 + 1] = p1 + b21;
                }
            }
        }
    }
}

// ---------------------------------------------------------------------------
extern "C" void kernel_launch(void* const* d_in, const int* in_sizes, int n_in,
                              void* d_out, int out_size) {
    const float* features = (const float*)d_in[0];
    const int*   ei       = (const int*)  d_in[1];
    const float* ew       = (const float*)d_in[2];
    const float* Wrel     = (const float*)d_in[3];
    const float* Wroot    = (const float*)d_in[4];
    const float* bias     = (const float*)d_in[5];
    const float* lng      = (const float*)d_in[6];
    const float* lnb      = (const float*)d_in[7];
    const float* alpha    = (const float*)d_in[8];
    const float* W1       = (const float*)d_in[9];
    const float* b1       = (const float*)d_in[10];
    const float* cg       = (const float*)d_in[11];
    const float* cb       = (const float*)d_in[12];
    const float* W2       = (const float*)d_in[13];
    const float* b2       = (const float*)d_in[14];

    int N = in_sizes[0] / DD;
    int E = in_sizes[1] / 2;
    int L = in_sizes[8];

    __half *h16a, *h16b, *agg16;
    int *cnt, *off, *bsum;
    uint2 *epack;
    cudaGetSymbolAddress((void**)&h16a,  g_h16a);
    cudaGetSymbolAddress((void**)&h16b,  g_h16b);
    cudaGetSymbolAddress((void**)&agg16, g_agg16);
    cudaGetSymbolAddress((void**)&cnt,   g_cnt);
    cudaGetSymbolAddress((void**)&off,   g_off);
    cudaGetSymbolAddress((void**)&bsum,  g_bsum);
    cudaGetSymbolAddress((void**)&epack, g_epack);

    int sm = 148;
    cudaDeviceGetAttribute(&sm, cudaDevAttrMultiProcessorCount, 0);

    size_t smemL = 65536;   // 2 x 32 KB fp16 B fragments
    size_t smemC = 32768;   // 32 KB
    cudaFuncSetAttribute(layer_mma_kernel, cudaFuncAttributeMaxDynamicSharedMemorySize, (int)smemL);
    cudaFuncSetAttribute(cls_mma_kernel,   cudaFuncAttributeMaxDynamicSharedMemorySize, (int)smemC);

    // ---- CSR build (no memsets; cnt self-restores) ----
    int NB = (N + 1023) / 1024;
    hist_kernel <<<(E + 255) / 256, 256>>>(ei, cnt, E);
    scan1_kernel<<<NB, 1024>>>(cnt, off, bsum, N);
    scan2_kernel<<<1, 128>>>(bsum, off, NB, N);
    place_kernel<<<(E + 255) / 256, 256>>>(ei, ew, off, bsum, cnt, epack, E);

    // fp16 features -> h16a
    int n4 = N * DD / 4;
    to_half_kernel<<<(n4 + 255) / 256, 256>>>((const float4*)features, (uint2*)h16a, n4);

    int gatherBlocks = (N + 7) / 8;

    __half* hin = h16a;
    __half* pong[2] = { h16b, h16a };
    for (int i = 0; i < L; i++) {
        __half* hout = pong[i & 1];
        gather_kernel<<<gatherBlocks, 256>>>(hin, off, bsum, epack, agg16, N);
        layer_mma_kernel<<<sm, 256, smemL>>>(hin, agg16,
                                             Wrel  + (size_t)i * DD * DD,
                                             Wroot + (size_t)i * DD * DD,
                                             bias + i * DD, lng + i * DD, lnb + i * DD,
                                             alpha + i, hout, N);
        hin = hout;
    }
    cls_mma_kernel<<<sm, 256, smemC>>>(hin, W1, b1, cg, cb, W2, b2,
                                       (float*)d_out, N);
}